// round 16
// baseline (speedup 1.0000x reference)
#include <cuda_runtime.h>
#include <cuda_fp16.h>
#include <mma.h>
#include <math.h>
#include <stdint.h>

using namespace nvcuda;

// ---------------------------------------------------------------------------
// Problem constants
// ---------------------------------------------------------------------------
#define BB 32
#define NN 1024
#define DD 768
#define E_TOKN 4
#define E_CHN 4
#define EE 8
#define TOPK 2
#define HNN 4096
#define HDD 3072
#define NPAIR (BB * TOPK)            // 64 selected (batch, expert) pairs
#define HID_ELEMS (DD * HNN)         // 3145728 == NN*HDD

// ---------------------------------------------------------------------------
// Static device scratch (uint4-typed: guaranteed 16B alignment).
// RULE (rounds 3-5 root cause): device-global addresses are formed ONLY in
// device code — host-side g_* is the shadow symbol (ATS makes it writable!).
// ---------------------------------------------------------------------------
__device__ float g_xm[BB * DD];
__device__ int   g_pair_e[NPAIR];
__device__ float g_pair_w[NPAIR];
__device__ int   g_tile_ctr;          // work-queue counter; reset by k_router

__device__ uint4 g_xf_raw  [BB * NN * DD / 8];          // x fp16 [b][n][d]
__device__ uint4 g_tw1f_raw[E_TOKN * HNN * NN / 8];
__device__ uint4 g_tw2f_raw[E_TOKN * NN * HNN / 8];
__device__ uint4 g_cw1f_raw[E_CHN * HDD * DD / 8];
__device__ uint4 g_cw2f_raw[E_CHN * DD * HDD / 8];
__device__ uint4 g_hidf_raw[(size_t)NPAIR * HID_ELEMS / 8];   // ~402 MB fp16

#define g_xf   ((__half*)g_xf_raw)
#define g_tw1f ((__half*)g_tw1f_raw)
#define g_tw2f ((__half*)g_tw2f_raw)
#define g_cw1f ((__half*)g_cw1f_raw)
#define g_cw2f ((__half*)g_cw2f_raw)
#define g_hidf ((__half*)g_hidf_raw)

// ---------------------------------------------------------------------------
// Helpers
// ---------------------------------------------------------------------------
__device__ __forceinline__ __half2 gelu2_h_scaled(float a, float b, __half2 ws) {
    const float c = 0.7978845608028654f;
    float ua = c * (a + 0.044715f * a * a * a);
    float ub = c * (b + 0.044715f * b * b * b);
    __half2 u2 = __floats2half2_rn(ua, ub);
    uint32_t uu = *reinterpret_cast<uint32_t*>(&u2);
    uint32_t tt;
    asm("tanh.approx.f16x2 %0, %1;" : "=r"(tt) : "r"(uu));
    __half2 t2 = *reinterpret_cast<__half2*>(&tt);
    __half2 vh = __floats2half2_rn(a, b);
    __half2 one  = __float2half2_rn(1.0f);
    __half2 half_ = __float2half2_rn(0.5f);
    __half2 g = __hmul2(__hmul2(half_, vh), __hadd2(one, t2));
    return __hmul2(g, ws);
}

__device__ __forceinline__ uint32_t smem_u32(const void* p) {
    uint32_t a;
    asm("{ .reg .u64 t; cvta.to.shared.u64 t, %1; cvt.u32.u64 %0, t; }"
        : "=r"(a) : "l"(p));
    return a;
}

#define CP_ASYNC16(dst32, src) \
    asm volatile("cp.async.cg.shared.global [%0], [%1], 16;" \
                 :: "r"(dst32), "l"(src) : "memory")
#define CP_COMMIT()  asm volatile("cp.async.commit_group;" ::: "memory")
#define CP_WAIT0()   asm volatile("cp.async.wait_group 0;" ::: "memory")

// ---------------------------------------------------------------------------
// Kernel: xm[b,d] = mean_n x[b,n,d]
// ---------------------------------------------------------------------------
__global__ void k_mean(const float* __restrict__ x) {
    int idx = blockIdx.x * blockDim.x + threadIdx.x;
    if (idx >= BB * DD) return;
    int b = idx / DD;
    int d = idx - b * DD;
    const float* p = x + (size_t)b * NN * DD + d;
    float s = 0.0f;
    #pragma unroll 8
    for (int n = 0; n < NN; n++) s += p[(size_t)n * DD];
    g_xm[idx] = s * (1.0f / (float)NN);
}

// ---------------------------------------------------------------------------
// Kernel: router logits, softmax, top-2, aux loss; also resets the L2 work
// queue counter (ordered before k_l2out on the stream -> valid every replay).
// ---------------------------------------------------------------------------
__global__ void k_router(const float* __restrict__ rw, float* __restrict__ out,
                         long long aux_idx, int has_aux) {
    __shared__ float probs[BB][EE];
    __shared__ int   top1s[BB];
    __shared__ float partial[EE];
    int t = threadIdx.x;

    if (t == 0) g_tile_ctr = 0;

    {
        int b = t >> 3, e = t & 7;
        const float* xm = g_xm + b * DD;
        const float* w  = rw + e * DD;
        float s = 0.0f;
        #pragma unroll 8
        for (int d = 0; d < DD; d++) s += xm[d] * w[d];
        probs[b][e] = s;
    }
    __syncthreads();

    if (t < BB) {
        float l[EE];
        float mx = -1e30f;
        #pragma unroll
        for (int e = 0; e < EE; e++) { l[e] = probs[t][e]; mx = fmaxf(mx, l[e]); }
        float sum = 0.0f;
        #pragma unroll
        for (int e = 0; e < EE; e++) { l[e] = expf(l[e] - mx); sum += l[e]; }
        float inv = 1.0f / sum;
        #pragma unroll
        for (int e = 0; e < EE; e++) { l[e] *= inv; probs[t][e] = l[e]; }
        int i0 = 0; float v0 = l[0];
        #pragma unroll
        for (int e = 1; e < EE; e++) if (l[e] > v0) { v0 = l[e]; i0 = e; }
        int i1 = -1; float v1 = -1e30f;
        #pragma unroll
        for (int e = 0; e < EE; e++) if (e != i0 && l[e] > v1) { v1 = l[e]; i1 = e; }
        float inv01 = 1.0f / (v0 + v1);
        g_pair_e[2 * t]     = i0; g_pair_w[2 * t]     = v0 * inv01;
        g_pair_e[2 * t + 1] = i1; g_pair_w[2 * t + 1] = v1 * inv01;
        top1s[t] = i0;
    }
    __syncthreads();

    if (t < EE) {
        float ps = 0.0f; int c = 0;
        for (int b = 0; b < BB; b++) { ps += probs[b][t]; c += (top1s[b] == t); }
        partial[t] = ps * (float)c;
    }
    __syncthreads();

    if (t == 0 && has_aux) {
        float s = 0.0f;
        #pragma unroll
        for (int e = 0; e < EE; e++) s += partial[e];
        out[aux_idx] = s * ((float)EE / ((float)BB * (float)BB));
    }
}

// ---------------------------------------------------------------------------
// Fused conversion kernel: all fp32 -> fp16 conversions.
// ---------------------------------------------------------------------------
#define NB_X   24576
#define NB_TW1 16384
#define NB_TW2 16384
#define NB_CW1 9216
#define NB_CW2 9216
#define NB_TOTAL (NB_X + NB_TW1 + NB_TW2 + NB_CW1 + NB_CW2)

__device__ __forceinline__ void cvt4(const float* __restrict__ s, __half* d, int i) {
    float4 v = ((const float4*)s)[i];
    __half2 a = __floats2half2_rn(v.x, v.y);
    __half2 b = __floats2half2_rn(v.z, v.w);
    uint2 u;
    u.x = *reinterpret_cast<uint32_t*>(&a);
    u.y = *reinterpret_cast<uint32_t*>(&b);
    ((uint2*)d)[i] = u;
}

__global__ void k_convert(const float* __restrict__ x,
                          const float* __restrict__ tw1,
                          const float* __restrict__ tw2,
                          const float* __restrict__ cw1,
                          const float* __restrict__ cw2) {
    int bid = blockIdx.x;
    int tid = threadIdx.x;

    if (bid < NB_X) {
        cvt4(x, g_xf, bid * 256 + tid);
    } else if (bid < NB_X + NB_TW1) {
        cvt4(tw1, g_tw1f, (bid - NB_X) * 256 + tid);
    } else if (bid < NB_X + NB_TW1 + NB_TW2) {
        cvt4(tw2, g_tw2f, (bid - NB_X - NB_TW1) * 256 + tid);
    } else if (bid < NB_X + NB_TW1 + NB_TW2 + NB_CW1) {
        cvt4(cw1, g_cw1f, (bid - NB_X - NB_TW1 - NB_TW2) * 256 + tid);
    } else {
        cvt4(cw2, g_cw2f, (bid - NB_X - NB_TW1 - NB_TW2 - NB_CW1) * 256 + tid);
    }
}

// ---------------------------------------------------------------------------
// GEMM accumulation core: adds A(128xK) * B(128xK)^T into acc.
// CTA 128x128, 128 threads = 4 warps (2x2), warp tile 64x64, BK=64,
// cp.async 2-stage, single __syncthreads per chunk, prefetch under MMAs.
// ACOLLD == 0: A row-major; ACOLLD > 0: A col-major with leading dim ACOLLD.
// ---------------------------------------------------------------------------
#define BK 64
#define RSTR 144
#define STRDH 72
#define CRSTR 272
#define CSTRDH 136
#define A_TILE_B (128 * RSTR)         // 18432
#define STAGE_B (2 * A_TILE_B)        // 36864
#define SMEM_PIPE (2 * STAGE_B)       // 73728
#define SMEM_L1 SMEM_PIPE
#define SMEM_L2 (SMEM_PIPE + 16)      // + control word for work queue

template<int K, int ACOLLD>
__device__ __forceinline__ void gemm_accum(
        wmma::fragment<wmma::accumulator, 16, 16, 16, float> (&acc)[4][4],
        const __half* pA, const __half* pB) {
    extern __shared__ __align__(128) unsigned char dsm[];
    const uint32_t sbase = smem_u32(dsm);
    const int tid = threadIdx.x, wid = tid >> 5;
    const int wm = wid & 1, wn = wid >> 1;

    auto load_stage = [&](int stage, int chk) {
        uint32_t sb = sbase + stage * STAGE_B;
        if (ACOLLD > 0) {
            #pragma unroll
            for (int it = 0; it < 8; it++) {
                int idx = it * 128 + tid;
                int row = idx >> 4, c = idx & 15;
                CP_ASYNC16(sb + row * CRSTR + c * 16,
                           pA + (size_t)(chk * BK + row) * ACOLLD + c * 8);
            }
        } else {
            #pragma unroll
            for (int it = 0; it < 8; it++) {
                int idx = it * 128 + tid;
                int row = idx >> 3, c = idx & 7;
                CP_ASYNC16(sb + row * RSTR + c * 16,
                           pA + (size_t)row * K + chk * BK + c * 8);
            }
        }
        #pragma unroll
        for (int it = 0; it < 8; it++) {
            int idx = it * 128 + tid;
            int row = idx >> 3, c = idx & 7;
            CP_ASYNC16(sb + A_TILE_B + row * RSTR + c * 16,
                       pB + (size_t)row * K + chk * BK + c * 8);
        }
        CP_COMMIT();
    };

    const int NCH = K / BK;
    load_stage(0, 0);

    for (int chk = 0; chk < NCH; chk++) {
        CP_WAIT0();
        __syncthreads();

        __half* sA = (__half*)(dsm + (chk & 1) * STAGE_B);
        __half* sB = (__half*)(dsm + (chk & 1) * STAGE_B + A_TILE_B);

        #pragma unroll
        for (int ks = 0; ks < BK / 16; ks++) {
            wmma::fragment<wmma::matrix_b, 16, 16, 16, __half, wmma::col_major> bf[4];
            #pragma unroll
            for (int p = 0; p < 4; p++)
                wmma::load_matrix_sync(bf[p], &sB[(wn * 64 + p * 16) * STRDH + ks * 16], STRDH);

            if (ACOLLD > 0) {
                wmma::fragment<wmma::matrix_a, 16, 16, 16, __half, wmma::col_major> af[4];
                #pragma unroll
                for (int mt = 0; mt < 4; mt++)
                    wmma::load_matrix_sync(af[mt],
                        &sA[(ks * 16) * CSTRDH + wm * 64 + mt * 16], CSTRDH);
                #pragma unroll
                for (int mt = 0; mt < 4; mt++)
                    #pragma unroll
                    for (int p = 0; p < 4; p++)
                        wmma::mma_sync(acc[mt][p], af[mt], bf[p], acc[mt][p]);
            } else {
                wmma::fragment<wmma::matrix_a, 16, 16, 16, __half, wmma::row_major> af[4];
                #pragma unroll
                for (int mt = 0; mt < 4; mt++)
                    wmma::load_matrix_sync(af[mt],
                        &sA[(wm * 64 + mt * 16) * STRDH + ks * 16], STRDH);
                #pragma unroll
                for (int mt = 0; mt < 4; mt++)
                    #pragma unroll
                    for (int p = 0; p < 4; p++)
                        wmma::mma_sync(acc[mt][p], af[mt], bf[p], acc[mt][p]);
            }
            if (ks == 0 && chk + 1 < NCH)
                load_stage((chk + 1) & 1, chk + 1);
        }
    }
}

// ---------------------------------------------------------------------------
// Merged L1 kernel: token + channel first layers; hidden written as fp16
// PRE-SCALED by the pair's routing weight.
// grid (192, 1, NPAIR): token 6(m) x 32(n) tiles; channel 8 x 24.
// ---------------------------------------------------------------------------
__global__ void __launch_bounds__(128, 3)
k_l1(const float* __restrict__ tb1, const float* __restrict__ cb1) {
    int p = blockIdx.z;
    int e = g_pair_e[p];
    int b = p >> 1;
    int bx = blockIdx.x;
    float w = g_pair_w[p];

    wmma::fragment<wmma::accumulator, 16, 16, 16, float> acc[4][4];
    #pragma unroll
    for (int mt = 0; mt < 4; mt++)
        #pragma unroll
        for (int q = 0; q < 4; q++) wmma::fill_fragment(acc[mt][q], 0.0f);

    int mT, nT, Nn;
    const float* bias;
    if (e < E_TOKN) {
        mT = (bx % 6) * 128; nT = (bx / 6) * 128; Nn = HNN;
        bias = tb1 + e * HNN;
        gemm_accum<NN, DD>(acc,
            g_xf + (size_t)b * NN * DD + mT,
            g_tw1f + (size_t)e * HNN * NN + (size_t)nT * NN);
    } else {
        int ec = e - E_TOKN;
        mT = (bx % 8) * 128; nT = (bx / 8) * 128; Nn = HDD;
        bias = cb1 + ec * HDD;
        gemm_accum<DD, 0>(acc,
            g_xf + (size_t)b * NN * DD + (size_t)mT * DD,
            g_cw1f + (size_t)ec * HDD * DD + (size_t)nT * DD);
    }

    extern __shared__ __align__(128) unsigned char dsm[];
    const int tid = threadIdx.x, lane = tid & 31, wid = tid >> 5;
    const int wm = wid & 1, wn = wid >> 1;
    float* st = (float*)dsm + wid * 288;
    const int r  = lane >> 1;
    const int c0 = (lane & 1) * 8;
    __half2 ws = __float2half2_rn(w);
    __half* Ch = g_hidf + (size_t)p * HID_ELEMS;

    #pragma unroll
    for (int mt = 0; mt < 4; mt++) {
        #pragma unroll
        for (int q = 0; q < 4; q++) {
            wmma::store_matrix_sync(st, acc[mt][q], 16, wmma::mem_row_major);
            __syncwarp();
            int row = mT + wm * 64 + mt * 16 + r;
            int col = nT + wn * 64 + q * 16 + c0;
            float v[8];
            #pragma unroll
            for (int j = 0; j < 8; j++)
                v[j] = st[r * 16 + c0 + j] + __ldg(&bias[col + j]);
            __half2 hv[4];
            #pragma unroll
            for (int j = 0; j < 4; j++)
                hv[j] = gelu2_h_scaled(v[2 * j], v[2 * j + 1], ws);
            *(uint4*)(Ch + (size_t)row * Nn + col) = *(uint4*)hv;
            __syncwarp();
        }
    }
}

// ---------------------------------------------------------------------------
// Persistent fused L2 + combine kernel: 444 resident CTAs pop tile indices
// from an atomic work queue (deterministic: each tile computed exactly once,
// tiles write disjoint output ranges; counter reset by k_router each launch).
// Tile t: b = t/48, bx = t%48, mT = (bx%8)*128, nT = (bx/8)*128.
// Both selected pairs of batch b accumulate into one accumulator (hidden is
// pre-scaled by w); weight-combined bias added; writes out directly.
// ---------------------------------------------------------------------------
#define L2_TILES (48 * BB)            // 1536
#define L2_GRID  444                  // 148 SMs x 3 CTAs

__global__ void __launch_bounds__(128, 3)
k_l2out(const float* __restrict__ tb2, const float* __restrict__ cb2,
        float* __restrict__ out) {
    extern __shared__ __align__(128) unsigned char dsm[];
    int* tilep = (int*)(dsm + SMEM_PIPE);
    const int tid = threadIdx.x, lane = tid & 31, wid = tid >> 5;
    const int wm = wid & 1, wn = wid >> 1;

    for (;;) {
        __syncthreads();                       // smem (pipe + tilep) quiesced
        if (tid == 0) *tilep = atomicAdd(&g_tile_ctr, 1);
        __syncthreads();
        int t = *tilep;
        if (t >= L2_TILES) break;

        int b  = t / 48;
        int bx = t - b * 48;
        int mT = (bx % 8) * 128, nT = (bx / 8) * 128;

        wmma::fragment<wmma::accumulator, 16, 16, 16, float> acc[4][4];
        #pragma unroll
        for (int mt = 0; mt < 4; mt++)
            #pragma unroll
            for (int q = 0; q < 4; q++) wmma::fill_fragment(acc[mt][q], 0.0f);

        int   pe[2];
        float pw[2];
        #pragma unroll
        for (int i = 0; i < 2; i++) {
            int p = 2 * b + i;
            pe[i] = g_pair_e[p];
            pw[i] = g_pair_w[p];
            if (pe[i] < E_TOKN) {
                gemm_accum<HNN, 0>(acc,
                    g_tw2f + (size_t)pe[i] * NN * HNN + (size_t)mT * HNN,
                    g_hidf + (size_t)p * HID_ELEMS + (size_t)nT * HNN);
            } else {
                int ec = pe[i] - E_TOKN;
                gemm_accum<HDD, 0>(acc,
                    g_hidf + (size_t)p * HID_ELEMS + (size_t)mT * HDD,
                    g_cw2f + (size_t)ec * DD * HDD + (size_t)nT * HDD);
            }
        }

        float* st = (float*)dsm + wid * 288;
        const int r  = lane >> 1;
        const int c0 = (lane & 1) * 8;
        float* outp = out + (size_t)b * NN * DD;

        #pragma unroll
        for (int mt = 0; mt < 4; mt++) {
            #pragma unroll
            for (int q = 0; q < 4; q++) {
                wmma::store_matrix_sync(st, acc[mt][q], 16, wmma::mem_row_major);
                __syncwarp();
                int row = mT + wm * 64 + mt * 16 + r;
                int col = nT + wn * 64 + q * 16 + c0;
                float v[8];
                #pragma unroll
                for (int j = 0; j < 8; j++) v[j] = st[r * 16 + c0 + j];
                #pragma unroll
                for (int i = 0; i < 2; i++) {
                    if (pe[i] < E_TOKN) {
                        float bb = pw[i] * __ldg(&tb2[pe[i] * NN + row]);
                        #pragma unroll
                        for (int j = 0; j < 8; j++) v[j] += bb;
                    } else {
                        int ec = pe[i] - E_TOKN;
                        #pragma unroll
                        for (int j = 0; j < 8; j++)
                            v[j] += pw[i] * __ldg(&cb2[ec * DD + col + j]);
                    }
                }
                *(float4*)(outp + (size_t)row * DD + col)     = *(float4*)&v[0];
                *(float4*)(outp + (size_t)row * DD + col + 4) = *(float4*)&v[4];
                __syncwarp();
            }
        }
    }
}

// ---------------------------------------------------------------------------
// Launch — only harness pointers cross host->device. ncu capture lands on
// launch index 3 = k_l1.
// ---------------------------------------------------------------------------
extern "C" void kernel_launch(void* const* d_in, const int* in_sizes, int n_in,
                              void* d_out, int out_size) {
    const float* x        = (const float*)d_in[0];
    const float* router_w = (const float*)d_in[1];
    const float* tok_w1   = (const float*)d_in[2];
    const float* tok_b1   = (const float*)d_in[3];
    const float* tok_w2   = (const float*)d_in[4];
    const float* tok_b2   = (const float*)d_in[5];
    const float* ch_w1    = (const float*)d_in[6];
    const float* ch_b1    = (const float*)d_in[7];
    const float* ch_w2    = (const float*)d_in[8];
    const float* ch_b2    = (const float*)d_in[9];
    float* out = (float*)d_out;

    long long bnd = (long long)BB * NN * DD;
    int has_aux = (long long)out_size > bnd;

    cudaFuncSetAttribute(k_l1,    cudaFuncAttributeMaxDynamicSharedMemorySize, SMEM_L1);
    cudaFuncSetAttribute(k_l2out, cudaFuncAttributeMaxDynamicSharedMemorySize, SMEM_L2);

    // 0: mean, 1: router (+ work-queue reset), 2: fused conversions
    k_mean<<<(BB * DD + 255) / 256, 256>>>(x);
    k_router<<<1, 256>>>(router_w, out, bnd, has_aux);
    k_convert<<<NB_TOTAL, 256>>>(x, tok_w1, tok_w2, ch_w1, ch_w2);

    // 3: merged L1 GEMM (writes weight-pre-scaled fp16 hidden)
    dim3 g_l1(192, 1, NPAIR);
    k_l1<<<g_l1, 128, SMEM_L1>>>(tok_b1, ch_b1);

    // 4: persistent fused L2 + combine (atomic work queue over 1536 tiles)
    k_l2out<<<L2_GRID, 128, SMEM_L2>>>(tok_b2, ch_b2, out);
}

// round 17
// speedup vs baseline: 1.0342x; 1.0342x over previous
#include <cuda_runtime.h>
#include <cuda_fp16.h>
#include <mma.h>
#include <math.h>
#include <stdint.h>

using namespace nvcuda;

// ---------------------------------------------------------------------------
// Problem constants
// ---------------------------------------------------------------------------
#define BB 32
#define NN 1024
#define DD 768
#define E_TOKN 4
#define E_CHN 4
#define EE 8
#define TOPK 2
#define HNN 4096
#define HDD 3072
#define NPAIR (BB * TOPK)            // 64 selected (batch, expert) pairs
#define HID_ELEMS (DD * HNN)         // 3145728 == NN*HDD

// ---------------------------------------------------------------------------
// Static device scratch (uint4-typed: guaranteed 16B alignment).
// RULE (rounds 3-5 root cause): device-global addresses are formed ONLY in
// device code — host-side g_* is the shadow symbol (ATS makes it writable!).
// ---------------------------------------------------------------------------
__device__ float g_xm[BB * DD];
__device__ int   g_pair_e[NPAIR];
__device__ float g_pair_w[NPAIR];
__device__ int   g_border[BB];        // LPT batch order for k_l2out

__device__ uint4 g_xf_raw  [BB * NN * DD / 8];          // x fp16 [b][n][d]
__device__ uint4 g_tw1f_raw[E_TOKN * HNN * NN / 8];
__device__ uint4 g_tw2f_raw[E_TOKN * NN * HNN / 8];
__device__ uint4 g_cw1f_raw[E_CHN * HDD * DD / 8];
__device__ uint4 g_cw2f_raw[E_CHN * DD * HDD / 8];
__device__ uint4 g_hidf_raw[(size_t)NPAIR * HID_ELEMS / 8];   // ~402 MB fp16

#define g_xf   ((__half*)g_xf_raw)
#define g_tw1f ((__half*)g_tw1f_raw)
#define g_tw2f ((__half*)g_tw2f_raw)
#define g_cw1f ((__half*)g_cw1f_raw)
#define g_cw2f ((__half*)g_cw2f_raw)
#define g_hidf ((__half*)g_hidf_raw)

// ---------------------------------------------------------------------------
// Helpers
// ---------------------------------------------------------------------------
__device__ __forceinline__ __half2 gelu2_h_scaled(float a, float b, __half2 ws) {
    const float c = 0.7978845608028654f;
    float ua = c * (a + 0.044715f * a * a * a);
    float ub = c * (b + 0.044715f * b * b * b);
    __half2 u2 = __floats2half2_rn(ua, ub);
    uint32_t uu = *reinterpret_cast<uint32_t*>(&u2);
    uint32_t tt;
    asm("tanh.approx.f16x2 %0, %1;" : "=r"(tt) : "r"(uu));
    __half2 t2 = *reinterpret_cast<__half2*>(&tt);
    __half2 vh = __floats2half2_rn(a, b);
    __half2 one  = __float2half2_rn(1.0f);
    __half2 half_ = __float2half2_rn(0.5f);
    __half2 g = __hmul2(__hmul2(half_, vh), __hadd2(one, t2));
    return __hmul2(g, ws);
}

__device__ __forceinline__ uint32_t smem_u32(const void* p) {
    uint32_t a;
    asm("{ .reg .u64 t; cvta.to.shared.u64 t, %1; cvt.u32.u64 %0, t; }"
        : "=r"(a) : "l"(p));
    return a;
}

#define CP_ASYNC16(dst32, src) \
    asm volatile("cp.async.cg.shared.global [%0], [%1], 16;" \
                 :: "r"(dst32), "l"(src) : "memory")
#define CP_COMMIT()  asm volatile("cp.async.commit_group;" ::: "memory")
#define CP_WAIT0()   asm volatile("cp.async.wait_group 0;" ::: "memory")

// ---------------------------------------------------------------------------
// Kernel: xm[b,d] = mean_n x[b,n,d]
// ---------------------------------------------------------------------------
__global__ void k_mean(const float* __restrict__ x) {
    int idx = blockIdx.x * blockDim.x + threadIdx.x;
    if (idx >= BB * DD) return;
    int b = idx / DD;
    int d = idx - b * DD;
    const float* p = x + (size_t)b * NN * DD + d;
    float s = 0.0f;
    #pragma unroll 8
    for (int n = 0; n < NN; n++) s += p[(size_t)n * DD];
    g_xm[idx] = s * (1.0f / (float)NN);
}

// ---------------------------------------------------------------------------
// Kernel: router logits, softmax, top-2, aux loss; also emits the LPT batch
// order for k_l2out (longest-K batches first -> shortest tiles fill the tail).
// ---------------------------------------------------------------------------
__global__ void k_router(const float* __restrict__ rw, float* __restrict__ out,
                         long long aux_idx, int has_aux) {
    __shared__ float probs[BB][EE];
    __shared__ int   top1s[BB];
    __shared__ float partial[EE];
    int t = threadIdx.x;

    {
        int b = t >> 3, e = t & 7;
        const float* xm = g_xm + b * DD;
        const float* w  = rw + e * DD;
        float s = 0.0f;
        #pragma unroll 8
        for (int d = 0; d < DD; d++) s += xm[d] * w[d];
        probs[b][e] = s;
    }
    __syncthreads();

    if (t < BB) {
        float l[EE];
        float mx = -1e30f;
        #pragma unroll
        for (int e = 0; e < EE; e++) { l[e] = probs[t][e]; mx = fmaxf(mx, l[e]); }
        float sum = 0.0f;
        #pragma unroll
        for (int e = 0; e < EE; e++) { l[e] = expf(l[e] - mx); sum += l[e]; }
        float inv = 1.0f / sum;
        #pragma unroll
        for (int e = 0; e < EE; e++) { l[e] *= inv; probs[t][e] = l[e]; }
        int i0 = 0; float v0 = l[0];
        #pragma unroll
        for (int e = 1; e < EE; e++) if (l[e] > v0) { v0 = l[e]; i0 = e; }
        int i1 = -1; float v1 = -1e30f;
        #pragma unroll
        for (int e = 0; e < EE; e++) if (e != i0 && l[e] > v1) { v1 = l[e]; i1 = e; }
        float inv01 = 1.0f / (v0 + v1);
        g_pair_e[2 * t]     = i0; g_pair_w[2 * t]     = v0 * inv01;
        g_pair_e[2 * t + 1] = i1; g_pair_w[2 * t + 1] = v1 * inv01;
        top1s[t] = i0;
    }
    __syncthreads();

    if (t < EE) {
        float ps = 0.0f; int c = 0;
        for (int b = 0; b < BB; b++) { ps += probs[b][t]; c += (top1s[b] == t); }
        partial[t] = ps * (float)c;
    }
    __syncthreads();

    if (t == 0) {
        if (has_aux) {
            float s = 0.0f;
            #pragma unroll
            for (int e = 0; e < EE; e++) s += partial[e];
            out[aux_idx] = s * ((float)EE / ((float)BB * (float)BB));
        }
        // LPT order: bucket batches by total K (2 token=8192, mixed=7168,
        // 2 channel=6144), longest first. Deterministic counting sort.
        int idx = 0;
        for (int pass = 0; pass < 3; pass++) {
            int want = 2 - pass;   // #token pairs: 2, 1, 0
            for (int b = 0; b < BB; b++) {
                int ntok = (g_pair_e[2 * b] < E_TOKN ? 1 : 0)
                         + (g_pair_e[2 * b + 1] < E_TOKN ? 1 : 0);
                if (ntok == want) g_border[idx++] = b;
            }
        }
    }
}

// ---------------------------------------------------------------------------
// Fused conversion kernel: all fp32 -> fp16 conversions.
// ---------------------------------------------------------------------------
#define NB_X   24576
#define NB_TW1 16384
#define NB_TW2 16384
#define NB_CW1 9216
#define NB_CW2 9216
#define NB_TOTAL (NB_X + NB_TW1 + NB_TW2 + NB_CW1 + NB_CW2)

__device__ __forceinline__ void cvt4(const float* __restrict__ s, __half* d, int i) {
    float4 v = ((const float4*)s)[i];
    __half2 a = __floats2half2_rn(v.x, v.y);
    __half2 b = __floats2half2_rn(v.z, v.w);
    uint2 u;
    u.x = *reinterpret_cast<uint32_t*>(&a);
    u.y = *reinterpret_cast<uint32_t*>(&b);
    ((uint2*)d)[i] = u;
}

__global__ void k_convert(const float* __restrict__ x,
                          const float* __restrict__ tw1,
                          const float* __restrict__ tw2,
                          const float* __restrict__ cw1,
                          const float* __restrict__ cw2) {
    int bid = blockIdx.x;
    int tid = threadIdx.x;

    if (bid < NB_X) {
        cvt4(x, g_xf, bid * 256 + tid);
    } else if (bid < NB_X + NB_TW1) {
        cvt4(tw1, g_tw1f, (bid - NB_X) * 256 + tid);
    } else if (bid < NB_X + NB_TW1 + NB_TW2) {
        cvt4(tw2, g_tw2f, (bid - NB_X - NB_TW1) * 256 + tid);
    } else if (bid < NB_X + NB_TW1 + NB_TW2 + NB_CW1) {
        cvt4(cw1, g_cw1f, (bid - NB_X - NB_TW1 - NB_TW2) * 256 + tid);
    } else {
        cvt4(cw2, g_cw2f, (bid - NB_X - NB_TW1 - NB_TW2 - NB_CW1) * 256 + tid);
    }
}

// ---------------------------------------------------------------------------
// GEMM accumulation core: adds A(128xK) * B(128xK)^T into acc.
// CTA 128x128, 128 threads = 4 warps (2x2), warp tile 64x64, BK=64,
// cp.async 2-stage, single __syncthreads per chunk, prefetch under MMAs.
// ACOLLD == 0: A row-major; ACOLLD > 0: A col-major with leading dim ACOLLD.
// ---------------------------------------------------------------------------
#define BK 64
#define RSTR 144
#define STRDH 72
#define CRSTR 272
#define CSTRDH 136
#define A_TILE_B (128 * RSTR)         // 18432
#define STAGE_B (2 * A_TILE_B)        // 36864
#define SMEM_TOT (2 * STAGE_B)        // 73728

template<int K, int ACOLLD>
__device__ __forceinline__ void gemm_accum(
        wmma::fragment<wmma::accumulator, 16, 16, 16, float> (&acc)[4][4],
        const __half* pA, const __half* pB) {
    extern __shared__ __align__(128) unsigned char dsm[];
    const uint32_t sbase = smem_u32(dsm);
    const int tid = threadIdx.x, wid = tid >> 5;
    const int wm = wid & 1, wn = wid >> 1;

    auto load_stage = [&](int stage, int chk) {
        uint32_t sb = sbase + stage * STAGE_B;
        if (ACOLLD > 0) {
            #pragma unroll
            for (int it = 0; it < 8; it++) {
                int idx = it * 128 + tid;
                int row = idx >> 4, c = idx & 15;
                CP_ASYNC16(sb + row * CRSTR + c * 16,
                           pA + (size_t)(chk * BK + row) * ACOLLD + c * 8);
            }
        } else {
            #pragma unroll
            for (int it = 0; it < 8; it++) {
                int idx = it * 128 + tid;
                int row = idx >> 3, c = idx & 7;
                CP_ASYNC16(sb + row * RSTR + c * 16,
                           pA + (size_t)row * K + chk * BK + c * 8);
            }
        }
        #pragma unroll
        for (int it = 0; it < 8; it++) {
            int idx = it * 128 + tid;
            int row = idx >> 3, c = idx & 7;
            CP_ASYNC16(sb + A_TILE_B + row * RSTR + c * 16,
                       pB + (size_t)row * K + chk * BK + c * 8);
        }
        CP_COMMIT();
    };

    const int NCH = K / BK;
    load_stage(0, 0);

    for (int chk = 0; chk < NCH; chk++) {
        CP_WAIT0();
        __syncthreads();

        __half* sA = (__half*)(dsm + (chk & 1) * STAGE_B);
        __half* sB = (__half*)(dsm + (chk & 1) * STAGE_B + A_TILE_B);

        #pragma unroll
        for (int ks = 0; ks < BK / 16; ks++) {
            wmma::fragment<wmma::matrix_b, 16, 16, 16, __half, wmma::col_major> bf[4];
            #pragma unroll
            for (int p = 0; p < 4; p++)
                wmma::load_matrix_sync(bf[p], &sB[(wn * 64 + p * 16) * STRDH + ks * 16], STRDH);

            if (ACOLLD > 0) {
                wmma::fragment<wmma::matrix_a, 16, 16, 16, __half, wmma::col_major> af[4];
                #pragma unroll
                for (int mt = 0; mt < 4; mt++)
                    wmma::load_matrix_sync(af[mt],
                        &sA[(ks * 16) * CSTRDH + wm * 64 + mt * 16], CSTRDH);
                #pragma unroll
                for (int mt = 0; mt < 4; mt++)
                    #pragma unroll
                    for (int p = 0; p < 4; p++)
                        wmma::mma_sync(acc[mt][p], af[mt], bf[p], acc[mt][p]);
            } else {
                wmma::fragment<wmma::matrix_a, 16, 16, 16, __half, wmma::row_major> af[4];
                #pragma unroll
                for (int mt = 0; mt < 4; mt++)
                    wmma::load_matrix_sync(af[mt],
                        &sA[(wm * 64 + mt * 16) * STRDH + ks * 16], STRDH);
                #pragma unroll
                for (int mt = 0; mt < 4; mt++)
                    #pragma unroll
                    for (int p = 0; p < 4; p++)
                        wmma::mma_sync(acc[mt][p], af[mt], bf[p], acc[mt][p]);
            }
            if (ks == 0 && chk + 1 < NCH)
                load_stage((chk + 1) & 1, chk + 1);
        }
    }
}

// ---------------------------------------------------------------------------
// Merged L1 kernel: token + channel first layers; hidden written as fp16
// PRE-SCALED by the pair's routing weight.
// grid (192, 1, NPAIR): token 6(m) x 32(n) tiles; channel 8 x 24.
// ---------------------------------------------------------------------------
__global__ void __launch_bounds__(128, 3)
k_l1(const float* __restrict__ tb1, const float* __restrict__ cb1) {
    int p = blockIdx.z;
    int e = g_pair_e[p];
    int b = p >> 1;
    int bx = blockIdx.x;
    float w = g_pair_w[p];

    wmma::fragment<wmma::accumulator, 16, 16, 16, float> acc[4][4];
    #pragma unroll
    for (int mt = 0; mt < 4; mt++)
        #pragma unroll
        for (int q = 0; q < 4; q++) wmma::fill_fragment(acc[mt][q], 0.0f);

    int mT, nT, Nn;
    const float* bias;
    if (e < E_TOKN) {
        // A = x[b] read col-major (A[m=d][k=n] = x[n][d], ld = DD)
        mT = (bx % 6) * 128; nT = (bx / 6) * 128; Nn = HNN;
        bias = tb1 + e * HNN;
        gemm_accum<NN, DD>(acc,
            g_xf + (size_t)b * NN * DD + mT,
            g_tw1f + (size_t)e * HNN * NN + (size_t)nT * NN);
    } else {
        int ec = e - E_TOKN;
        mT = (bx % 8) * 128; nT = (bx / 8) * 128; Nn = HDD;
        bias = cb1 + ec * HDD;
        gemm_accum<DD, 0>(acc,
            g_xf + (size_t)b * NN * DD + (size_t)mT * DD,
            g_cw1f + (size_t)ec * HDD * DD + (size_t)nT * DD);
    }

    extern __shared__ __align__(128) unsigned char dsm[];
    const int tid = threadIdx.x, lane = tid & 31, wid = tid >> 5;
    const int wm = wid & 1, wn = wid >> 1;
    float* st = (float*)dsm + wid * 288;
    const int r  = lane >> 1;
    const int c0 = (lane & 1) * 8;
    __half2 ws = __float2half2_rn(w);
    __half* Ch = g_hidf + (size_t)p * HID_ELEMS;

    #pragma unroll
    for (int mt = 0; mt < 4; mt++) {
        #pragma unroll
        for (int q = 0; q < 4; q++) {
            wmma::store_matrix_sync(st, acc[mt][q], 16, wmma::mem_row_major);
            __syncwarp();
            int row = mT + wm * 64 + mt * 16 + r;
            int col = nT + wn * 64 + q * 16 + c0;
            float v[8];
            #pragma unroll
            for (int j = 0; j < 8; j++)
                v[j] = st[r * 16 + c0 + j] + __ldg(&bias[col + j]);
            __half2 hv[4];
            #pragma unroll
            for (int j = 0; j < 4; j++)
                hv[j] = gelu2_h_scaled(v[2 * j], v[2 * j + 1], ws);
            *(uint4*)(Ch + (size_t)row * Nn + col) = *(uint4*)hv;
            __syncwarp();
        }
    }
}

// ---------------------------------------------------------------------------
// Fused L2 + combine kernel: per batch, BOTH selected pairs accumulate
// sequentially into one accumulator (hidden is pre-scaled by w), then the
// weight-combined bias is added and the result written straight to out.
// grid (48, 1, BB); batch remapped via LPT order (longest batches launch
// first; shortest fill the final partial wave). Deterministic.
// ---------------------------------------------------------------------------
__global__ void __launch_bounds__(128, 3)
k_l2out(const float* __restrict__ tb2, const float* __restrict__ cb2,
        float* __restrict__ out) {
    int b  = g_border[blockIdx.z];
    int bx = blockIdx.x;
    int mT = (bx % 8) * 128, nT = (bx / 8) * 128;

    wmma::fragment<wmma::accumulator, 16, 16, 16, float> acc[4][4];
    #pragma unroll
    for (int mt = 0; mt < 4; mt++)
        #pragma unroll
        for (int q = 0; q < 4; q++) wmma::fill_fragment(acc[mt][q], 0.0f);

    int   pe[2];
    float pw[2];
    #pragma unroll
    for (int i = 0; i < 2; i++) {
        int p = 2 * b + i;
        pe[i] = g_pair_e[p];
        pw[i] = g_pair_w[p];
        if (pe[i] < E_TOKN) {
            gemm_accum<HNN, 0>(acc,
                g_tw2f + (size_t)pe[i] * NN * HNN + (size_t)mT * HNN,
                g_hidf + (size_t)p * HID_ELEMS + (size_t)nT * HNN);
        } else {
            int ec = pe[i] - E_TOKN;
            gemm_accum<HDD, 0>(acc,
                g_hidf + (size_t)p * HID_ELEMS + (size_t)mT * HDD,
                g_cw2f + (size_t)ec * DD * HDD + (size_t)nT * HDD);
        }
    }

    extern __shared__ __align__(128) unsigned char dsm[];
    const int tid = threadIdx.x, lane = tid & 31, wid = tid >> 5;
    const int wm = wid & 1, wn = wid >> 1;
    float* st = (float*)dsm + wid * 288;
    const int r  = lane >> 1;
    const int c0 = (lane & 1) * 8;
    float* outp = out + (size_t)b * NN * DD;

    #pragma unroll
    for (int mt = 0; mt < 4; mt++) {
        #pragma unroll
        for (int q = 0; q < 4; q++) {
            wmma::store_matrix_sync(st, acc[mt][q], 16, wmma::mem_row_major);
            __syncwarp();
            int row = mT + wm * 64 + mt * 16 + r;
            int col = nT + wn * 64 + q * 16 + c0;
            float v[8];
            #pragma unroll
            for (int j = 0; j < 8; j++) v[j] = st[r * 16 + c0 + j];
            #pragma unroll
            for (int i = 0; i < 2; i++) {
                if (pe[i] < E_TOKN) {
                    float bb = pw[i] * __ldg(&tb2[pe[i] * NN + row]);
                    #pragma unroll
                    for (int j = 0; j < 8; j++) v[j] += bb;
                } else {
                    int ec = pe[i] - E_TOKN;
                    #pragma unroll
                    for (int j = 0; j < 8; j++)
                        v[j] += pw[i] * __ldg(&cb2[ec * DD + col + j]);
                }
            }
            *(float4*)(outp + (size_t)row * DD + col)     = *(float4*)&v[0];
            *(float4*)(outp + (size_t)row * DD + col + 4) = *(float4*)&v[4];
            __syncwarp();
        }
    }
}

// ---------------------------------------------------------------------------
// Launch — only harness pointers cross host->device. ncu capture lands on
// launch index 3 = k_l1.
// ---------------------------------------------------------------------------
extern "C" void kernel_launch(void* const* d_in, const int* in_sizes, int n_in,
                              void* d_out, int out_size) {
    const float* x        = (const float*)d_in[0];
    const float* router_w = (const float*)d_in[1];
    const float* tok_w1   = (const float*)d_in[2];
    const float* tok_b1   = (const float*)d_in[3];
    const float* tok_w2   = (const float*)d_in[4];
    const float* tok_b2   = (const float*)d_in[5];
    const float* ch_w1    = (const float*)d_in[6];
    const float* ch_b1    = (const float*)d_in[7];
    const float* ch_w2    = (const float*)d_in[8];
    const float* ch_b2    = (const float*)d_in[9];
    float* out = (float*)d_out;

    long long bnd = (long long)BB * NN * DD;
    int has_aux = (long long)out_size > bnd;

    cudaFuncSetAttribute(k_l1,    cudaFuncAttributeMaxDynamicSharedMemorySize, SMEM_TOT);
    cudaFuncSetAttribute(k_l2out, cudaFuncAttributeMaxDynamicSharedMemorySize, SMEM_TOT);

    // 0: mean, 1: router (+ LPT batch order), 2: fused conversions
    k_mean<<<(BB * DD + 255) / 256, 256>>>(x);
    k_router<<<1, 256>>>(router_w, out, bnd, has_aux);
    k_convert<<<NB_TOTAL, 256>>>(x, tok_w1, tok_w2, ch_w1, ch_w2);

    // 3: merged L1 GEMM (writes weight-pre-scaled fp16 hidden)
    dim3 g_l1(192, 1, NPAIR);
    k_l1<<<g_l1, 128, SMEM_TOT>>>(tok_b1, ch_b1);

    // 4: fused L2 + combine (HW-scheduled, LPT batch order)
    dim3 g_l2o(48, 1, BB);
    k_l2out<<<g_l2o, 128, SMEM_TOT>>>(tok_b2, ch_b2, out);
}